// round 2
// baseline (speedup 1.0000x reference)
#include <cuda_runtime.h>
#include <cstdint>

// ---------------------------------------------------------------------------
// MixedGNN on GB300.
//   NOTE: JAX default config disables x64 -> batch / edge_index are INT32.
//   Phase A: per-graph global encoder (128 rows)  -> g_HG, g_GM
//   Phase B: per-node encoder + mix + msg + self  -> g_m, g_aggr(=m), g_s
//   Phase C: edge scatter: aggr[dst] += m[src]    (red.global.add.v4.f32)
//   Phase D: out = relu(aggr + s) @ W_out + b_out
// ---------------------------------------------------------------------------

#define NMAX 200000
#define BMAX 1024
#define HID  32

__device__ __align__(16) float g_HG[BMAX * HID];   // relu(x_global @ W_global + b_global)
__device__ __align__(16) float g_GM[BMAX * HID];   // g_HG @ W_mix[32:64] + b_mix
__device__ __align__(16) float g_m   [NMAX * HID]; // relu(h0 @ W_msg + b_msg)
__device__ __align__(16) float g_aggr[NMAX * HID]; // segment-sum target (init = m, self loop)
__device__ __align__(16) float g_s   [NMAX * HID]; // h0 @ W_self + b_self

typedef unsigned long long u64;

// ---- f32x2 packed math (Blackwell; ptxas won't emit FFMA2 from C++) -------
__device__ __forceinline__ u64 splat2(float x) {
    u64 r;
    asm("mov.b64 %0, {%1, %1};" : "=l"(r) : "r"(__float_as_uint(x)));
    return r;
}
__device__ __forceinline__ void ffma2(u64& d, u64 a, u64 b) {
    asm("fma.rn.f32x2 %0, %1, %2, %0;" : "+l"(d) : "l"(a), "l"(b));
}
__device__ __forceinline__ float2 unpack2(u64 v) {
    unsigned lo, hi;
    asm("mov.b64 {%0, %1}, %2;" : "=r"(lo), "=r"(hi) : "l"(v));
    return make_float2(__uint_as_float(lo), __uint_as_float(hi));
}

// ---------------------------------------------------------------------------
// Kernel A: global-graph encoder + precomputed mix contribution.
// ---------------------------------------------------------------------------
__global__ void k_global(const float* __restrict__ xg,
                         const float* __restrict__ Wg, const float* __restrict__ bg,
                         const float* __restrict__ Wmix, const float* __restrict__ bmix,
                         int B) {
    int b = blockIdx.x * blockDim.x + threadIdx.x;
    if (b >= B) return;
    float x[8];
#pragma unroll
    for (int k = 0; k < 8; k++) x[k] = xg[b * 8 + k];
    float h[HID];
#pragma unroll
    for (int j = 0; j < HID; j++) {
        float a = bg[j];
#pragma unroll
        for (int k = 0; k < 8; k++) a = fmaf(x[k], Wg[k * HID + j], a);
        h[j] = fmaxf(a, 0.f);
        g_HG[b * HID + j] = h[j];
    }
#pragma unroll 4
    for (int j = 0; j < HID; j++) {
        float a = bmix[j];
#pragma unroll
        for (int k = 0; k < HID; k++) a = fmaf(h[k], Wmix[(32 + k) * HID + j], a);
        g_GM[b * HID + j] = a;
    }
}

// ---------------------------------------------------------------------------
// Kernel B: per-node pipeline (one thread per node).
// ---------------------------------------------------------------------------
__global__ void __launch_bounds__(128)
k_node(const float* __restrict__ x_local,
       const int* __restrict__ batch,
       const float* __restrict__ W_local, const float* __restrict__ b_local,
       const float* __restrict__ W_mix,
       const float* __restrict__ W_msg, const float* __restrict__ b_msg,
       const float* __restrict__ W_self, const float* __restrict__ b_self,
       int N) {
    __shared__ __align__(16) float sWl[16 * HID];     // W_local
    __shared__ __align__(16) float sWm1[HID * HID];   // W_mix rows 0..31   (h_local part)
    __shared__ __align__(16) float sWm3[HID * HID];   // W_mix rows 64..95  (h_int part)
    __shared__ __align__(16) float sWmsg[HID * HID];
    __shared__ __align__(16) float sWself[HID * HID];
    __shared__ __align__(16) float sb[3 * HID];       // b_local | b_msg | b_self

    for (int i = threadIdx.x; i < 16 * HID; i += blockDim.x) sWl[i] = W_local[i];
    for (int i = threadIdx.x; i < HID * HID; i += blockDim.x) {
        sWm1[i]   = W_mix[i];
        sWm3[i]   = W_mix[64 * HID + i];
        sWmsg[i]  = W_msg[i];
        sWself[i] = W_self[i];
    }
    for (int i = threadIdx.x; i < HID; i += blockDim.x) {
        sb[i]           = b_local[i];
        sb[HID + i]     = b_msg[i];
        sb[2 * HID + i] = b_self[i];
    }
    __syncthreads();

    int n = blockIdx.x * blockDim.x + threadIdx.x;
    if (n >= N) return;

    // ---- load x_local row (16 floats) ----
    float xl[16];
    {
        const float4* p = (const float4*)(x_local + (size_t)n * 16);
#pragma unroll
        for (int i = 0; i < 4; i++) {
            float4 v = p[i];
            xl[4 * i + 0] = v.x; xl[4 * i + 1] = v.y;
            xl[4 * i + 2] = v.z; xl[4 * i + 3] = v.w;
        }
    }

    // ---- h_local = relu(xl @ W_local + b_local) ----
    float hl[HID];
    {
        u64 acc[16];
        const u64* bb = (const u64*)&sb[0];
#pragma unroll
        for (int jj = 0; jj < 16; jj++) acc[jj] = bb[jj];
#pragma unroll
        for (int k = 0; k < 16; k++) {
            u64 xs = splat2(xl[k]);
            const u64* w = (const u64*)&sWl[k * HID];
#pragma unroll
            for (int jj = 0; jj < 16; jj++) ffma2(acc[jj], xs, w[jj]);
        }
#pragma unroll
        for (int jj = 0; jj < 16; jj++) {
            float2 p = unpack2(acc[jj]);
            hl[2 * jj]     = fmaxf(p.x, 0.f);
            hl[2 * jj + 1] = fmaxf(p.y, 0.f);
        }
    }

    // ---- gather h_global row ----
    int b = batch[n];
    float hg[HID];
    {
        const float4* p = (const float4*)&g_HG[b * HID];
#pragma unroll
        for (int i = 0; i < 8; i++) {
            float4 v = p[i];
            hg[4 * i + 0] = v.x; hg[4 * i + 1] = v.y;
            hg[4 * i + 2] = v.z; hg[4 * i + 3] = v.w;
        }
    }

    // ---- h0 = relu(hl@Wm1 + (hl*hg)@Wm3 + g_GM[b]) ----
    float h0[HID];
    {
        u64 acc[16];
        const u64* gm = (const u64*)&g_GM[b * HID];
#pragma unroll
        for (int jj = 0; jj < 16; jj++) acc[jj] = gm[jj];
#pragma unroll 8
        for (int k = 0; k < HID; k++) {
            u64 s1 = splat2(hl[k]);
            u64 s2 = splat2(hl[k] * hg[k]);
            const u64* w1 = (const u64*)&sWm1[k * HID];
            const u64* w3 = (const u64*)&sWm3[k * HID];
#pragma unroll
            for (int jj = 0; jj < 16; jj++) {
                ffma2(acc[jj], s1, w1[jj]);
                ffma2(acc[jj], s2, w3[jj]);
            }
        }
#pragma unroll
        for (int jj = 0; jj < 16; jj++) {
            float2 p = unpack2(acc[jj]);
            h0[2 * jj]     = fmaxf(p.x, 0.f);
            h0[2 * jj + 1] = fmaxf(p.y, 0.f);
        }
    }

    // ---- m = relu(h0@W_msg + b_msg);  s = h0@W_self + b_self ----
    {
        u64 am[16], as_[16];
        const u64* bm = (const u64*)&sb[HID];
        const u64* bs = (const u64*)&sb[2 * HID];
#pragma unroll
        for (int jj = 0; jj < 16; jj++) { am[jj] = bm[jj]; as_[jj] = bs[jj]; }
#pragma unroll 8
        for (int k = 0; k < HID; k++) {
            u64 s0 = splat2(h0[k]);
            const u64* wm = (const u64*)&sWmsg[k * HID];
            const u64* ws = (const u64*)&sWself[k * HID];
#pragma unroll
            for (int jj = 0; jj < 16; jj++) {
                ffma2(am[jj], s0, wm[jj]);
                ffma2(as_[jj], s0, ws[jj]);
            }
        }
        float4* pm = (float4*)&g_m[(size_t)n * HID];
        float4* pa = (float4*)&g_aggr[(size_t)n * HID];
        float4* ps = (float4*)&g_s[(size_t)n * HID];
#pragma unroll
        for (int q = 0; q < 8; q++) {
            float2 p0 = unpack2(am[2 * q]);
            float2 p1 = unpack2(am[2 * q + 1]);
            float4 vm = make_float4(fmaxf(p0.x, 0.f), fmaxf(p0.y, 0.f),
                                    fmaxf(p1.x, 0.f), fmaxf(p1.y, 0.f));
            pm[q] = vm;
            pa[q] = vm;   // self-loop: aggr starts at m[n]
            float2 q0 = unpack2(as_[2 * q]);
            float2 q1 = unpack2(as_[2 * q + 1]);
            ps[q] = make_float4(q0.x, q0.y, q1.x, q1.y);
        }
    }
}

// ---------------------------------------------------------------------------
// Kernel C: edge scatter.  8 lanes per edge, each lane handles one float4 of
// the 32-float m[src] row -> red.global.add.v4.f32 into aggr[dst].
// ---------------------------------------------------------------------------
__global__ void __launch_bounds__(256)
k_edge(const int* __restrict__ ei, int E) {
    long long t = (long long)blockIdx.x * blockDim.x + threadIdx.x;
    int e = (int)(t >> 3);
    if (e >= E) return;
    int part = (int)(t & 7);
    int src = ei[e];
    int dst = ei[E + e];
    const float4* pm = (const float4*)g_m;
    float4 v = __ldg(&pm[(size_t)src * 8 + part]);
    float* a = g_aggr + ((size_t)dst * HID + part * 4);
    asm volatile("red.global.add.v4.f32 [%0], {%1, %2, %3, %4};"
                 :: "l"(a), "f"(v.x), "f"(v.y), "f"(v.z), "f"(v.w)
                 : "memory");
}

// ---------------------------------------------------------------------------
// Kernel D: h = relu(aggr + s);  out = h @ W_out + b_out   ([N,2])
// ---------------------------------------------------------------------------
__global__ void __launch_bounds__(256)
k_final(const float* __restrict__ W_out, const float* __restrict__ b_out,
        float* __restrict__ out, int N) {
    __shared__ float sw[HID * 2];
    __shared__ float sbo[2];
    if (threadIdx.x < HID * 2) sw[threadIdx.x] = W_out[threadIdx.x];
    if (threadIdx.x < 2) sbo[threadIdx.x] = b_out[threadIdx.x];
    __syncthreads();

    int n = blockIdx.x * blockDim.x + threadIdx.x;
    if (n >= N) return;

    const float4* pa = (const float4*)&g_aggr[(size_t)n * HID];
    const float4* ps = (const float4*)&g_s[(size_t)n * HID];
    float acc0 = sbo[0], acc1 = sbo[1];
#pragma unroll
    for (int q = 0; q < 8; q++) {
        float4 a = pa[q];
        float4 s = ps[q];
        float h0 = fmaxf(a.x + s.x, 0.f);
        float h1 = fmaxf(a.y + s.y, 0.f);
        float h2 = fmaxf(a.z + s.z, 0.f);
        float h3 = fmaxf(a.w + s.w, 0.f);
        int j = q * 4;
        acc0 = fmaf(h0, sw[(j + 0) * 2 + 0], acc0);
        acc1 = fmaf(h0, sw[(j + 0) * 2 + 1], acc1);
        acc0 = fmaf(h1, sw[(j + 1) * 2 + 0], acc0);
        acc1 = fmaf(h1, sw[(j + 1) * 2 + 1], acc1);
        acc0 = fmaf(h2, sw[(j + 2) * 2 + 0], acc0);
        acc1 = fmaf(h2, sw[(j + 2) * 2 + 1], acc1);
        acc0 = fmaf(h3, sw[(j + 3) * 2 + 0], acc0);
        acc1 = fmaf(h3, sw[(j + 3) * 2 + 1], acc1);
    }
    ((float2*)out)[n] = make_float2(acc0, acc1);
}

// ---------------------------------------------------------------------------
// Launch
// ---------------------------------------------------------------------------
extern "C" void kernel_launch(void* const* d_in, const int* in_sizes, int n_in,
                              void* d_out, int out_size) {
    const float* x_local  = (const float*)d_in[0];
    const float* x_global = (const float*)d_in[1];
    const int*   batch    = (const int*)d_in[2];     // int32 (JAX x64 disabled)
    const int*   ei       = (const int*)d_in[3];     // int32 (JAX x64 disabled)
    const float* W_local  = (const float*)d_in[4];
    const float* b_local  = (const float*)d_in[5];
    const float* W_global = (const float*)d_in[6];
    const float* b_global = (const float*)d_in[7];
    const float* W_mix    = (const float*)d_in[8];
    const float* b_mix    = (const float*)d_in[9];
    const float* W_msg    = (const float*)d_in[10];
    const float* b_msg    = (const float*)d_in[11];
    const float* W_self   = (const float*)d_in[12];
    const float* b_self   = (const float*)d_in[13];
    const float* W_out    = (const float*)d_in[14];
    const float* b_out    = (const float*)d_in[15];
    float*       out      = (float*)d_out;

    int N = in_sizes[0] / 16;
    int B = in_sizes[1] / 8;
    int E = in_sizes[3] / 2;

    // A: global encoder (tiny)
    k_global<<<(B + 127) / 128, 128>>>(x_global, W_global, b_global, W_mix, b_mix, B);

    // B: node pipeline
    k_node<<<(N + 127) / 128, 128>>>(x_local, batch, W_local, b_local, W_mix,
                                     W_msg, b_msg, W_self, b_self, N);

    // C: edge scatter (8 threads per edge)
    long long tot = (long long)E * 8;
    int blocks = (int)((tot + 255) / 256);
    k_edge<<<blocks, 256>>>(ei, E);

    // D: output head
    k_final<<<(N + 255) / 256, 256>>>(W_out, b_out, out, N);
}